// round 16
// baseline (speedup 1.0000x reference)
#include <cuda_runtime.h>
#include <cuda_bf16.h>
#include <cuda_fp16.h>
#include <stdint.h>

#define DM 1024
#define NH 16
#define DK 64
#define SEQ 2048
#define MTOT 4096
#define NBH 32
#define NX (MTOT*DM)
#define NW (DM*DM)

// scratch arena (raw 2-byte storage)
__device__ __nv_bfloat16 g_buf[14ull*NX + 8ull*NW];

#define OFF_XQ  0ull
#define OFF_XK  (1ull*NX)
#define OFF_XV  (2ull*NX)
#define OFF_W   (6ull*NX)
#define OFF_QF  (OFF_W + 8ull*NW)
#define OFF_KF  (OFF_QF + 2ull*NX)
#define OFF_VF  (OFF_QF + 4ull*NX)   /* fp16, transposed [b,h,d,s] */
#define OFF_CF  (OFF_QF + 6ull*NX)

static __device__ __forceinline__ uint32_t smem_u32(const void* p) {
    uint32_t a;
    asm("{ .reg .u64 t; cvta.to.shared.u64 t, %1; cvt.u32.u64 %0, t; }" : "=r"(a) : "l"(p));
    return a;
}

#define MMAH(C, A, B) asm volatile( \
    "mma.sync.aligned.m16n8k16.row.col.f32.f16.f16.f32 " \
    "{%0,%1,%2,%3}, {%4,%5,%6,%7}, {%8,%9}, {%0,%1,%2,%3};" \
    : "+f"((C)[0]), "+f"((C)[1]), "+f"((C)[2]), "+f"((C)[3]) \
    : "r"((A)[0]), "r"((A)[1]), "r"((A)[2]), "r"((A)[3]), \
      "r"((B)[0]), "r"((B)[1]))

#define LDM4(R, ADDR) asm volatile( \
    "ldmatrix.sync.aligned.m8n8.x4.shared.b16 {%0,%1,%2,%3}, [%4];" \
    : "=r"((R)[0]), "=r"((R)[1]), "=r"((R)[2]), "=r"((R)[3]) : "r"(ADDR))

#define CP16(d, s) asm volatile("cp.async.cg.shared.global [%0], [%1], 16;" :: "r"(d), "l"(s))
#define CPC()   asm volatile("cp.async.commit_group;")
#define CPW(n)  asm volatile("cp.async.wait_group %0;" :: "n"(n))

#define SWC(row, ch) (((row) << 6) + ((((ch) ^ (((row) >> 1) & 3))) << 4))
#define SWK(row, ch) (((row) << 7) + ((((ch) ^ ((row) & 7))) << 4))

static __device__ __forceinline__ uint32_t pack_h2(float x0, float x1) {
    __half2 h = __floats2half2_rn(x0, x1);
    return *(uint32_t*)&h;
}

// ---------------------------------------------------------------------------
struct ConvArgs {
    const float4* s[7];
    uint4* o[7];
    int nch[7];
};
__global__ void conv_multi(ConvArgs a)
{
    const int y = blockIdx.y;
    int i = blockIdx.x * blockDim.x + threadIdx.x;
    if (i >= a.nch[y]) return;
    const float4* src = a.s[y];
    float4 p = src[i*2], q = src[i*2+1];
    uint4 O;
    O.x = pack_h2(p.x, p.y);
    O.y = pack_h2(p.z, p.w);
    O.z = pack_h2(q.x, q.y);
    O.w = pack_h2(q.z, q.w);
    a.o[y][i] = O;
}

// ---------------------------------------------------------------------------
// Batched GEMM: Y = A @ W^T + bias. fp16 single operands.
// CTA 128x128, warp tile 32x64, k-step 64, 3-stage cp.async, 1 sync/iter,
// prefetch distance 2. 2 CTAs/SM.
// ---------------------------------------------------------------------------
struct GemmArgs {
    const __half* ah[3];
    const __half* wf[3];
    const float* bias[3];
    float* yf[3];
    __half* yh[3];
    int mode[3];
};
#define G_SUB    16384    /* A 8K + B 8K */
#define G_STAGE  32768
#define GEMM_SMEM (3*G_STAGE)   /* 98304 */
__global__ void __launch_bounds__(256, 2) gemm_mma(GemmArgs ga)
{
    extern __shared__ char sm[];
    const uint32_t sb = smem_u32(sm);
    const int z = blockIdx.z;
    const int t = threadIdx.x, lane = t & 31, w = t >> 5;
    const int wm = w & 3, wn = w >> 2;
    const int n0 = blockIdx.x * 128, m0 = blockIdx.y * 128;
    const int mode = ga.mode[z];
    const float* bias = ga.bias[z];

    const __half* aSrc = ga.ah[z] + (size_t)m0 * DM;
    const __half* bSrc = ga.wf[z] + (size_t)n0 * DM;

    const int lrow = t >> 2, lch = t & 3;

#define G_LOAD(kt, st) do { \
    _Pragma("unroll") \
    for (int s_2 = 0; s_2 < 2; s_2++) { \
        uint32_t ab = sb + (st)*G_STAGE + s_2*G_SUB; \
        _Pragma("unroll") \
        for (int j_ = 0; j_ < 2; j_++) { \
            int r_ = lrow + j_*64; \
            CP16(ab + SWC(r_, lch), aSrc + (size_t)r_ * DM + (kt) + s_2*32 + lch*8); \
        } \
        uint32_t bb = ab + 8192; \
        _Pragma("unroll") \
        for (int j_ = 0; j_ < 2; j_++) { \
            int r_ = lrow + j_*64; \
            CP16(bb + SWC(r_, lch), bSrc + (size_t)r_ * DM + (kt) + s_2*32 + lch*8); \
        } \
    } \
} while (0)

    float acc[2][8][4];
    #pragma unroll
    for (int i = 0; i < 2; i++)
        #pragma unroll
        for (int j = 0; j < 8; j++)
            #pragma unroll
            for (int k = 0; k < 4; k++) acc[i][j][k] = 0.f;

    const int aRow0 = wm*32 + (lane & 15);
    const int aChH  = lane >> 4;
    const int bRowOff = wn*64 + (lane & 7) + ((lane >> 4) << 3);
    const int bChH  = (lane >> 3) & 1;

    G_LOAD(0, 0);  CPC();
    G_LOAD(64, 1); CPC();

    int st = 0;
    #pragma unroll 1
    for (int kc = 0; kc < 16; kc++) {
        CPW(1);
        __syncthreads();
        if (kc + 2 < 16) {
            int wr = st - 1 < 0 ? 2 : st - 1;
            G_LOAD((kc + 2) * 64, wr);
        }
        CPC();

        #pragma unroll
        for (int sub = 0; sub < 2; sub++) {
            const uint32_t uA = sb + st*G_STAGE + sub*G_SUB;
            const uint32_t uB = uA + 8192;
            #pragma unroll
            for (int ks = 0; ks < 2; ks++) {
                const int c = ks*2 + aChH;
                uint32_t aF[2][4];
                LDM4(aF[0], uA + SWC(aRow0,      c));
                LDM4(aF[1], uA + SWC(aRow0 + 16, c));
                const int cb = ks*2 + bChH;
                #pragma unroll
                for (int nt2 = 0; nt2 < 4; nt2++) {
                    int r = bRowOff + nt2*16;
                    uint32_t rv[4];
                    LDM4(rv, uB + SWC(r, cb));
                    uint32_t b0[2] = {rv[0], rv[1]}, b1[2] = {rv[2], rv[3]};
                    const int nA = nt2*2, nB = nt2*2 + 1;
                    MMAH(acc[0][nA], aF[0], b0);
                    MMAH(acc[0][nB], aF[0], b1);
                    MMAH(acc[1][nA], aF[1], b0);
                    MMAH(acc[1][nB], aF[1], b1);
                }
            }
        }
        st = st + 1 == 3 ? 0 : st + 1;
    }

    // ---- epilogue ----
    float* Yf = ga.yf[z];
    __half* Yh = ga.yh[z];
    const int g = lane >> 2, tig = lane & 3;
    #pragma unroll
    for (int mt = 0; mt < 2; mt++) {
        const int r0 = m0 + wm*32 + mt*16 + g;
        float v[2][8][2];
        #pragma unroll
        for (int nt = 0; nt < 8; nt++) {
            int col = n0 + wn*64 + nt*8 + tig*2;
            float b0v = bias[col], b1v = bias[col + 1];
            v[0][nt][0] = acc[mt][nt][0] + b0v;
            v[0][nt][1] = acc[mt][nt][1] + b1v;
            v[1][nt][0] = acc[mt][nt][2] + b0v;
            v[1][nt][1] = acc[mt][nt][3] + b1v;
        }
        if (mode == 0) {
            #pragma unroll
            for (int rr = 0; rr < 2; rr++) {
                int r = r0 + rr*8;
                #pragma unroll
                for (int nt = 0; nt < 8; nt++) {
                    int col = n0 + wn*64 + nt*8 + tig*2;
                    *(float2*)(Yf + (size_t)r * DM + col) =
                        make_float2(v[rr][nt][0], v[rr][nt][1]);
                }
            }
        } else {
            if (mode == 3) {
                #pragma unroll
                for (int rr = 0; rr < 2; rr++) {
                    float ss = 0.f;
                    #pragma unroll
                    for (int nt = 0; nt < 8; nt++)
                        ss += v[rr][nt][0]*v[rr][nt][0] + v[rr][nt][1]*v[rr][nt][1];
                    ss += __shfl_xor_sync(0xffffffffu, ss, 1);
                    ss += __shfl_xor_sync(0xffffffffu, ss, 2);
                    float inv = rsqrtf(ss + 1e-8f);
                    #pragma unroll
                    for (int nt = 0; nt < 8; nt++) {
                        v[rr][nt][0] *= inv;
                        v[rr][nt][1] *= inv;
                    }
                }
            }
            const int h_ = (n0 >> 6) + wn;
            const int b_ = r0 >> 11;
            #pragma unroll
            for (int rr = 0; rr < 2; rr++) {
                const int s_ = (r0 + rr*8) & 2047;
                if (mode == 1) {
                    const size_t base = (size_t)(b_ * NH + h_) * DK;
                    #pragma unroll
                    for (int nt = 0; nt < 8; nt++) {
                        int d = nt*8 + tig*2;
                        Yh[(base + d    ) * SEQ + s_] = __float2half(v[rr][nt][0]);
                        Yh[(base + d + 1) * SEQ + s_] = __float2half(v[rr][nt][1]);
                    }
                } else {
                    const size_t base = ((size_t)(b_ * NH + h_) * SEQ + s_) * DK;
                    #pragma unroll
                    for (int nt = 0; nt < 8; nt++)
                        *(uint32_t*)(Yh + base + nt*8 + tig*2) =
                            pack_h2(v[rr][nt][0], v[rr][nt][1]);
                }
            }
        }
    }
#undef G_LOAD
}

// ---------------------------------------------------------------------------
// Attention: 128-thread CTA, 4 warps x 32 q-rows, q-tile 128,
// 128 keys/iter (two 64-key sub-chunks), 2-stage, 1 sync/iter.
// ---------------------------------------------------------------------------
#define A_QARR  16384
#define A_SUB   8192
#define A_STAGE 32768   /* K0 K1 V0 V1 */
#define ATTN_SMEM (A_QARR + 2*A_STAGE)   /* 81920 */
__global__ void __launch_bounds__(128, 2) attn_mma(
    const __half* __restrict__ qfp, const __half* __restrict__ kfp,
    const __half* __restrict__ vfp, __half* __restrict__ cf)
{
    extern __shared__ char sm[];
    const uint32_t sb = smem_u32(sm);
    const int t = threadIdx.x, lane = t & 31, w = t >> 5;
    const int q0 = blockIdx.x * 128;
    const int bh = blockIdx.y;
    const size_t base = (size_t)bh * SEQ * DK;

    const __half* Ksrc = kfp + base;
    const __half* Vsrc = vfp + base;

    const int krow = t >> 1, kc0 = (t & 1) * 4;   // 64 rows, 4 chunks each

#define A_LOADKV(kt, st) do { \
    _Pragma("unroll") \
    for (int s_2 = 0; s_2 < 2; s_2++) { \
        uint32_t kb = sb + A_QARR + (st)*A_STAGE + s_2*A_SUB; \
        _Pragma("unroll") \
        for (int c_ = 0; c_ < 4; c_++) \
            CP16(kb + SWK(krow, kc0 + c_), \
                 Ksrc + (size_t)((kt) + s_2*64 + krow) * DK + (kc0 + c_)*8); \
        uint32_t vb = sb + A_QARR + (st)*A_STAGE + 16384 + s_2*A_SUB; \
        _Pragma("unroll") \
        for (int c_ = 0; c_ < 4; c_++) \
            CP16(vb + SWK(krow, kc0 + c_), \
                 Vsrc + (size_t)krow * SEQ + (kt) + s_2*64 + (kc0 + c_)*8); \
    } \
} while (0)

    // Q loads: 128 rows x 8 chunks
    {
        const __half* Qsrc = qfp + base;
        #pragma unroll
        for (int i = 0; i < 8; i++) {
            int c = t + i*128, row = c >> 3, chn = c & 7;
            CP16(sb + SWK(row, chn), Qsrc + (size_t)(q0 + row) * DK + chn*8);
        }
    }
    A_LOADKV(0, 0);  CPC();

    const int aRow0 = w*32 + (lane & 15);
    const int aChH = lane >> 4;
    const int bRowOff = (lane & 7) + ((lane >> 4) << 3);
    const int bChH = (lane >> 3) & 1;

    float o[2][8][4];
    #pragma unroll
    for (int m = 0; m < 2; m++)
        #pragma unroll
        for (int i = 0; i < 8; i++)
            #pragma unroll
            for (int j = 0; j < 4; j++) o[m][i][j] = 0.f;

    #pragma unroll 1
    for (int kc = 0; kc < 16; kc++) {
        const int st = kc & 1;
        CPW(0);
        __syncthreads();
        if (kc + 1 < 16) A_LOADKV((kc + 1) * 128, st ^ 1);
        CPC();

        #pragma unroll
        for (int sub = 0; sub < 2; sub++) {
            const uint32_t uKf = sb + A_QARR + st*A_STAGE + sub*A_SUB;
            const uint32_t uVf = sb + A_QARR + st*A_STAGE + 16384 + sub*A_SUB;

            float s[2][8][4];
            #pragma unroll
            for (int m = 0; m < 2; m++)
                #pragma unroll
                for (int i = 0; i < 8; i++)
                    #pragma unroll
                    for (int j = 0; j < 4; j++) s[m][i][j] = 0.f;

            #pragma unroll
            for (int ks = 0; ks < 4; ks++) {
                const int qc = ks*2 + aChH;
                uint32_t aQ[2][4];
                LDM4(aQ[0], sb + SWK(aRow0,      qc));
                LDM4(aQ[1], sb + SWK(aRow0 + 16, qc));
                const int cb = ks*2 + bChH;
                #pragma unroll
                for (int nt2 = 0; nt2 < 4; nt2++) {
                    int r = bRowOff + nt2*16;
                    uint32_t rk[4];
                    LDM4(rk, uKf + SWK(r, cb));
                    uint32_t b0[2] = {rk[0], rk[1]}, b1[2] = {rk[2], rk[3]};
                    const int nA = nt2*2, nB = nt2*2 + 1;
                    MMAH(s[0][nA], aQ[0], b0); MMAH(s[0][nB], aQ[0], b1);
                    MMAH(s[1][nA], aQ[1], b0); MMAH(s[1][nB], aQ[1], b1);
                }
            }

            #pragma unroll
            for (int kt2 = 0; kt2 < 4; kt2++) {
                uint32_t aP[2][4];
                #pragma unroll
                for (int m = 0; m < 2; m++) {
                    aP[m][0] = pack_h2(s[m][2*kt2][0]*s[m][2*kt2][0],     s[m][2*kt2][1]*s[m][2*kt2][1]);
                    aP[m][1] = pack_h2(s[m][2*kt2][2]*s[m][2*kt2][2],     s[m][2*kt2][3]*s[m][2*kt2][3]);
                    aP[m][2] = pack_h2(s[m][2*kt2+1][0]*s[m][2*kt2+1][0], s[m][2*kt2+1][1]*s[m][2*kt2+1][1]);
                    aP[m][3] = pack_h2(s[m][2*kt2+1][2]*s[m][2*kt2+1][2], s[m][2*kt2+1][3]*s[m][2*kt2+1][3]);
                }
                const int cb = kt2*2 + bChH;
                #pragma unroll
                for (int nt2 = 0; nt2 < 4; nt2++) {
                    int r = bRowOff + nt2*16;
                    uint32_t rv[4];
                    LDM4(rv, uVf + SWK(r, cb));
                    uint32_t b0[2] = {rv[0], rv[1]}, b1[2] = {rv[2], rv[3]};
                    const int nA = nt2*2, nB = nt2*2 + 1;
                    MMAH(o[0][nA], aP[0], b0); MMAH(o[0][nB], aP[0], b1);
                    MMAH(o[1][nA], aP[1], b0); MMAH(o[1][nB], aP[1], b1);
                }
            }
        }
    }

    // ctx epilogue: fp16 single, [b, s, DM]
    const int g = lane >> 2, tig = lane & 3;
    const int b_ = bh >> 4, h_ = bh & 15;
    #pragma unroll
    for (int mt = 0; mt < 2; mt++) {
        const int r0 = q0 + w*32 + mt*16 + g;
        #pragma unroll
        for (int rr = 0; rr < 2; rr++) {
            const int s_ = r0 + rr*8;
            const size_t ob = ((size_t)b_ * SEQ + s_) * DM + h_ * DK;
            #pragma unroll
            for (int nt = 0; nt < 8; nt++)
                *(uint32_t*)(cf + ob + nt*8 + tig*2) =
                    pack_h2(o[mt][nt][rr*2], o[mt][nt][rr*2+1]);
        }
    }
#undef A_LOADKV
}

// ---------------------------------------------------------------------------
extern "C" void kernel_launch(void* const* d_in, const int* in_sizes, int n_in,
                              void* d_out, int out_size)
{
    const float* Q    = (const float*)d_in[0];
    const float* K    = (const float*)d_in[1];
    const float* V    = (const float*)d_in[2];
    const float* Wq_w = (const float*)d_in[3];
    const float* Wq_b = (const float*)d_in[4];
    const float* Wk_w = (const float*)d_in[5];
    const float* Wk_b = (const float*)d_in[6];
    const float* Wv_w = (const float*)d_in[7];
    const float* Wv_b = (const float*)d_in[8];
    const float* Wo_w = (const float*)d_in[9];
    const float* Wo_b = (const float*)d_in[10];
    float* out = (float*)d_out;

    __nv_bfloat16* gb;
    cudaGetSymbolAddress((void**)&gb, g_buf);

    __half* xf[3] = { (__half*)(gb + OFF_XQ), (__half*)(gb + OFF_XK), (__half*)(gb + OFF_XV) };
    __half* wf[4];
    for (int i = 0; i < 4; i++) wf[i] = (__half*)(gb + OFF_W) + (size_t)i * NW;
    __half *qf = (__half*)(gb + OFF_QF);
    __half *kf = (__half*)(gb + OFF_KF);
    __half *vf = (__half*)(gb + OFF_VF);
    __half *cf = (__half*)(gb + OFF_CF);

    cudaFuncSetAttribute(gemm_mma, cudaFuncAttributeMaxDynamicSharedMemorySize, GEMM_SMEM);
    cudaFuncSetAttribute(attn_mma, cudaFuncAttributeMaxDynamicSharedMemorySize, ATTN_SMEM);

    ConvArgs ca;
    ca.s[0] = (const float4*)Q;    ca.o[0] = (uint4*)xf[0]; ca.nch[0] = NX/8;
    ca.s[1] = (const float4*)K;    ca.o[1] = (uint4*)xf[1]; ca.nch[1] = NX/8;
    ca.s[2] = (const float4*)V;    ca.o[2] = (uint4*)xf[2]; ca.nch[2] = NX/8;
    ca.s[3] = (const float4*)Wq_w; ca.o[3] = (uint4*)wf[0]; ca.nch[3] = NW/8;
    ca.s[4] = (const float4*)Wk_w; ca.o[4] = (uint4*)wf[1]; ca.nch[4] = NW/8;
    ca.s[5] = (const float4*)Wv_w; ca.o[5] = (uint4*)wf[2]; ca.nch[5] = NW/8;
    ca.s[6] = (const float4*)Wo_w; ca.o[6] = (uint4*)wf[3]; ca.nch[6] = NW/8;
    conv_multi<<<dim3(NX/8/256, 7), 256>>>(ca);

    GemmArgs gqkv;
    gqkv.ah[0] = xf[0]; gqkv.wf[0] = wf[0];
    gqkv.bias[0] = Wq_b; gqkv.yf[0] = nullptr; gqkv.yh[0] = qf; gqkv.mode[0] = 3;
    gqkv.ah[1] = xf[1]; gqkv.wf[1] = wf[1];
    gqkv.bias[1] = Wk_b; gqkv.yf[1] = nullptr; gqkv.yh[1] = kf; gqkv.mode[1] = 3;
    gqkv.ah[2] = xf[2]; gqkv.wf[2] = wf[2];
    gqkv.bias[2] = Wv_b; gqkv.yf[2] = nullptr; gqkv.yh[2] = vf; gqkv.mode[2] = 1;
    gemm_mma<<<dim3(DM/128, MTOT/128, 3), 256, GEMM_SMEM>>>(gqkv);

    dim3 agrid(SEQ/128, NBH);
    attn_mma<<<agrid, 128, ATTN_SMEM>>>(qf, kf, vf, cf);

    GemmArgs go;
    go.ah[0] = cf; go.wf[0] = wf[3];
    go.bias[0] = Wo_b; go.yf[0] = out; go.yh[0] = nullptr; go.mode[0] = 0;
    go.ah[1] = go.ah[0]; go.wf[1] = go.wf[0];
    go.bias[1] = go.bias[0]; go.yf[1] = go.yf[0]; go.yh[1] = nullptr; go.mode[1] = 0;
    go.ah[2] = go.ah[0]; go.wf[2] = go.wf[0];
    go.bias[2] = go.bias[0]; go.yf[2] = go.yf[0]; go.yh[2] = nullptr; go.mode[2] = 0;
    gemm_mma<<<dim3(DM/128, MTOT/128, 1), 256, GEMM_SMEM>>>(go);
}